// round 15
// baseline (speedup 1.0000x reference)
#include <cuda_runtime.h>
#include <cuda_fp16.h>
#include <math.h>

#define NN     20000
#define FIN    128
#define HC     256
#define NHEADS 8
#define HID    32
#define NE     320000
#define ET     (NE + NN)
#define NG     64
#define NCLS   10

typedef unsigned int u32;

// fp16 tensor-core MMA: m16n8k16, fp32 accumulate
__device__ __forceinline__ void mma_f16(float* d, const u32* a, const u32* b) {
    asm("mma.sync.aligned.m16n8k16.row.col.f32.f16.f16.f32 "
        "{%0,%1,%2,%3}, {%4,%5,%6,%7}, {%8,%9}, {%0,%1,%2,%3};"
        : "+f"(d[0]), "+f"(d[1]), "+f"(d[2]), "+f"(d[3])
        : "r"(a[0]), "r"(a[1]), "r"(a[2]), "r"(a[3]), "r"(b[0]), "r"(b[1]));
}

__device__ __forceinline__ u32 pkh2(float lo, float hi) {
    __half2 h = __floats2half2_rn(lo, hi);
    return *(u32*)&h;
}

// load 8 halves -> two float4
__device__ __forceinline__ void ld8h(const __half* p, float4& a, float4& b) {
    uint4 q = *(const uint4*)p;
    float2 f0 = __half22float2(*(__half2*)&q.x);
    float2 f1 = __half22float2(*(__half2*)&q.y);
    float2 f2 = __half22float2(*(__half2*)&q.z);
    float2 f3 = __half22float2(*(__half2*)&q.w);
    a = make_float4(f0.x, f0.y, f1.x, f1.y);
    b = make_float4(f2.x, f2.y, f3.x, f3.y);
}

// dot of 8 packed halves with fp32 vectors
__device__ __forceinline__ float dot8(uint4 q, float4 xi0, float4 xi1) {
    float2 f0 = __half22float2(*(__half2*)&q.x);
    float2 f1 = __half22float2(*(__half2*)&q.y);
    float2 f2 = __half22float2(*(__half2*)&q.z);
    float2 f3 = __half22float2(*(__half2*)&q.w);
    return xi0.x * f0.x + xi0.y * f0.y + xi0.z * f1.x + xi0.w * f1.y
         + xi1.x * f2.x + xi1.y * f2.y + xi1.z * f3.x + xi1.w * f3.y;
}

// acc += wt * unpack(q)
__device__ __forceinline__ void axpy8(uint4 q, float wt, float4& a0, float4& a1) {
    float2 f0 = __half22float2(*(__half2*)&q.x);
    float2 f1 = __half22float2(*(__half2*)&q.y);
    float2 f2 = __half22float2(*(__half2*)&q.z);
    float2 f3 = __half22float2(*(__half2*)&q.w);
    a0.x += wt * f0.x;  a0.y += wt * f0.y;  a0.z += wt * f1.x;  a0.w += wt * f1.y;
    a1.x += wt * f2.x;  a1.y += wt * f2.y;  a1.z += wt * f3.x;  a1.w += wt * f3.y;
}

// ---------------- scratch ----------------
__device__ __align__(16) __half g_hh[(size_t)NN * HC];    // h (post-GEMM) fp16
__device__ __align__(16) __half g_bufh[(size_t)NN * HC];  // layer output fp16
__device__ float g_aL[NN * NHEADS];
__device__ float g_aR[NN * NHEADS];
__device__ int   g_deg[NN];
__device__ int   g_off[NN + 1];
__device__ int   g_cur[NN];
__device__ int   g_csr[ET];
__device__ int   g_is64;

// ---------------- dtype probe + zero scratch ----------------
__global__ void init_kernel(const int* __restrict__ ei_words) {
    int i = blockIdx.x * blockDim.x + threadIdx.x;
    if (i < NN) g_deg[i] = 0;
    if (blockIdx.x == 0 && threadIdx.x < 64) {
        int w = ei_words[2 * threadIdx.x + 1];
        unsigned nz = __ballot_sync(0xffffffffu, w != 0);
        if (threadIdx.x == 0) g_is64 = (nz == 0u) ? 1 : 0;
    }
}

__device__ __forceinline__ int load_idx(const void* p, long long i) {
    return g_is64 ? (int)((const long long*)p)[i] : ((const int*)p)[i];
}

// ---------------- CSR build (4 edges / thread for MLP) ----------------
__global__ void hist_kernel(const void* __restrict__ ei) {
    int base = (blockIdx.x * blockDim.x + threadIdx.x) * 4;
    if (base >= ET) return;
    int dst[4];
#pragma unroll
    for (int u = 0; u < 4; u++) {
        int e = base + u;
        dst[u] = (e < ET) ? ((e < NE) ? load_idx(ei, (long long)NE + e) : (e - NE)) : -1;
    }
#pragma unroll
    for (int u = 0; u < 4; u++)
        if (dst[u] >= 0) atomicAdd(&g_deg[dst[u]], 1);
}

__global__ void scan_kernel() {
    __shared__ int s[1024];
    const int CH = 20;
    int t = threadIdx.x;
    int base = t * CH;
    int sum = 0;
#pragma unroll
    for (int c = 0; c < CH; c++) {
        int i = base + c;
        if (i < NN) sum += g_deg[i];
    }
    s[t] = sum;
    __syncthreads();
    for (int o = 1; o < 1024; o <<= 1) {
        int v = (t >= o) ? s[t - o] : 0;
        __syncthreads();
        s[t] += v;
        __syncthreads();
    }
    int pre = s[t] - sum;
#pragma unroll
    for (int c = 0; c < CH; c++) {
        int i = base + c;
        if (i < NN) {
            g_off[i] = pre;
            g_cur[i] = pre;
            pre += g_deg[i];
        }
    }
    if (t == 1023) g_off[NN] = s[1023];
}

__global__ void fill_kernel(const void* __restrict__ ei) {
    int base = (blockIdx.x * blockDim.x + threadIdx.x) * 4;
    if (base >= ET) return;
    int src[4], dst[4];
#pragma unroll
    for (int u = 0; u < 4; u++) {
        int e = base + u;
        if (e < ET) {
            if (e < NE) { src[u] = load_idx(ei, e); dst[u] = load_idx(ei, (long long)NE + e); }
            else        { src[u] = dst[u] = e - NE; }
        } else dst[u] = -1;
    }
#pragma unroll
    for (int u = 0; u < 4; u++) {
        if (dst[u] >= 0) {
            int pos = atomicAdd(&g_cur[dst[u]], 1);
            g_csr[pos] = src[u];
        }
    }
}

// ---------------- fp16 tensor-core GEMM ----------------
// 128x64 block tile, 8 warps (warp 32x32 = 2x4 m16n8k16 atoms), KT=32 double-buffered.
#define KT 32

__global__ __launch_bounds__(256)
void gemm_kernel(const float* __restrict__ Aext, const float* __restrict__ B,
                 const float* __restrict__ attl, const float* __restrict__ attr,
                 int M, int K, int srcSel) {
    __shared__ __align__(16) u32 aS[2][128][20];   // [m][k2]
    __shared__ __align__(16) u32 bT[2][64][20];    // [n][k2]
    int tid  = threadIdx.x;
    int lane = tid & 31;
    int wid  = tid >> 5;
    int warpM = wid & 3;
    int warpN = wid >> 2;
    int m0 = blockIdx.y * 128, n0 = blockIdx.x * 64;

    const int ar  = tid >> 1;
    const int acg = (tid & 1) * 16;
    const int ach = (tid & 1) * 8;
    const int bg  = tid >> 4;
    const int bnc = (tid & 15) * 4;
    const int gmA = m0 + ar;

    uint4 rA0, rA1;
    float4 fBa, fBb;

    auto loadA = [&](int kb) {
        if (gmA < M) {
            if (srcSel) {
                const __half* p = g_bufh + (size_t)gmA * K + kb + acg;
                rA0 = *(const uint4*)p;
                rA1 = *(const uint4*)(p + 8);
            } else {
                const float* p = Aext + (size_t)gmA * K + kb + acg;
                float4 f0 = *(const float4*)p, f1 = *(const float4*)(p + 4);
                float4 f2 = *(const float4*)(p + 8), f3 = *(const float4*)(p + 12);
                rA0 = make_uint4(pkh2(f0.x, f0.y), pkh2(f0.z, f0.w),
                                 pkh2(f1.x, f1.y), pkh2(f1.z, f1.w));
                rA1 = make_uint4(pkh2(f2.x, f2.y), pkh2(f2.z, f2.w),
                                 pkh2(f3.x, f3.y), pkh2(f3.z, f3.w));
            }
        } else {
            rA0 = make_uint4(0, 0, 0, 0);
            rA1 = make_uint4(0, 0, 0, 0);
        }
    };
    auto loadB = [&](int kb) {
        fBa = *(const float4*)&B[(size_t)(kb + 2 * bg) * HC + n0 + bnc];
        fBb = *(const float4*)&B[(size_t)(kb + 2 * bg + 1) * HC + n0 + bnc];
    };
    auto stage = [&](int buf) {
        *(uint4*)&aS[buf][ar][ach]     = rA0;
        *(uint4*)&aS[buf][ar][ach + 4] = rA1;
        bT[buf][bnc + 0][bg] = pkh2(fBa.x, fBb.x);
        bT[buf][bnc + 1][bg] = pkh2(fBa.y, fBb.y);
        bT[buf][bnc + 2][bg] = pkh2(fBa.z, fBb.z);
        bT[buf][bnc + 3][bg] = pkh2(fBa.w, fBb.w);
    };

    loadA(0); loadB(0);
    stage(0);
    __syncthreads();

    float d[2][4][4] = {};
    const int r4 = lane >> 2, c4 = lane & 3;
    const int mBase = warpM * 32;
    const int nBase = warpN * 32;
    const int nT = K / KT;
    for (int t = 0; t < nT; t++) {
        int cur = t & 1, nxt = cur ^ 1;
        bool has = (t + 1 < nT);
        if (has) { loadA((t + 1) * KT); loadB((t + 1) * KT); }
#pragma unroll
        for (int s = 0; s < 2; s++) {
            int kc = s * 8 + c4;
            u32 afr[2][4];
            u32 bfr[4][2];
#pragma unroll
            for (int ma = 0; ma < 2; ma++) {
                int r0 = mBase + ma * 16 + r4;
                afr[ma][0] = aS[cur][r0][kc];
                afr[ma][1] = aS[cur][r0 + 8][kc];
                afr[ma][2] = aS[cur][r0][kc + 4];
                afr[ma][3] = aS[cur][r0 + 8][kc + 4];
            }
#pragma unroll
            for (int na = 0; na < 4; na++) {
                int nn = nBase + na * 8 + r4;
                bfr[na][0] = bT[cur][nn][kc];
                bfr[na][1] = bT[cur][nn][kc + 4];
            }
#pragma unroll
            for (int ma = 0; ma < 2; ma++)
#pragma unroll
                for (int na = 0; na < 4; na++)
                    mma_f16(d[ma][na], afr[ma], bfr[na]);
        }
        if (has) stage(nxt);
        __syncthreads();
    }

    // ---------------- epilogue: store h (fp16) + fused aL/aR ----------------
    int head = (n0 >> 5) + warpN;
    int c2 = (lane & 3) * 2;
    float lv[4][2], rv[4][2];
#pragma unroll
    for (int na = 0; na < 4; na++)
#pragma unroll
        for (int j = 0; j < 2; j++) {
            int colG = n0 + warpN * 32 + na * 8 + c2 + j;
            lv[na][j] = attl[colG];
            rv[na][j] = attr[colG];
        }
#pragma unroll
    for (int ma = 0; ma < 2; ma++) {
        int rbase = m0 + warpM * 32 + ma * 16 + (lane >> 2);
        float sl0 = 0.f, sl1 = 0.f, sr0 = 0.f, sr1 = 0.f;
#pragma unroll
        for (int na = 0; na < 4; na++) {
            sl0 += d[ma][na][0] * lv[na][0] + d[ma][na][1] * lv[na][1];
            sl1 += d[ma][na][2] * lv[na][0] + d[ma][na][3] * lv[na][1];
            sr0 += d[ma][na][0] * rv[na][0] + d[ma][na][1] * rv[na][1];
            sr1 += d[ma][na][2] * rv[na][0] + d[ma][na][3] * rv[na][1];
        }
        sl0 += __shfl_xor_sync(0xffffffffu, sl0, 1);  sl0 += __shfl_xor_sync(0xffffffffu, sl0, 2);
        sl1 += __shfl_xor_sync(0xffffffffu, sl1, 1);  sl1 += __shfl_xor_sync(0xffffffffu, sl1, 2);
        sr0 += __shfl_xor_sync(0xffffffffu, sr0, 1);  sr0 += __shfl_xor_sync(0xffffffffu, sr0, 2);
        sr1 += __shfl_xor_sync(0xffffffffu, sr1, 1);  sr1 += __shfl_xor_sync(0xffffffffu, sr1, 2);
        if ((lane & 3) == 0) {
            if (rbase < M)     { g_aL[rbase * NHEADS + head] = sl0;  g_aR[rbase * NHEADS + head] = sr0; }
            if (rbase + 8 < M) { g_aL[(rbase + 8) * NHEADS + head] = sl1;  g_aR[(rbase + 8) * NHEADS + head] = sr1; }
        }
#pragma unroll
        for (int na = 0; na < 4; na++) {
            int col = n0 + warpN * 32 + na * 8 + c2;
            if (rbase < M)
                *(__half2*)&g_hh[(size_t)rbase * HC + col] = __floats2half2_rn(d[ma][na][0], d[ma][na][1]);
            if (rbase + 8 < M)
                *(__half2*)&g_hh[(size_t)(rbase + 8) * HC + col] = __floats2half2_rn(d[ma][na][2], d[ma][na][3]);
        }
    }
}

// ---------------- fused edge-attention + softmax + aggregate (8-edge batches) ----------------
__global__ __launch_bounds__(256)
void attn_kernel(const float* __restrict__ bias, int applyElu) {
    int w = (blockIdx.x * blockDim.x + threadIdx.x) >> 5;
    if (w >= NN) return;
    int lane = threadIdx.x & 31;
    int head = lane >> 2;
    const __half* h = g_hh;
    float4 xi0, xi1;
    ld8h(h + (size_t)w * HC + lane * 8, xi0, xi1);
    float aRi = g_aR[w * NHEADS + head];
    float d = 0.f;
    float4 a0 = make_float4(0.f, 0.f, 0.f, 0.f);
    float4 a1 = make_float4(0.f, 0.f, 0.f, 0.f);
    int s = g_off[w], e = g_off[w + 1];
    int k = s;
    for (; k + 7 < e; k += 8) {
        int j[8];
        uint4 q[8];                 // packed fp16: 8 gathers in flight
        float aL[8], pd[8];
#pragma unroll
        for (int u = 0; u < 8; u++) j[u] = g_csr[k + u];
#pragma unroll
        for (int u = 0; u < 8; u++)
            q[u] = *(const uint4*)(h + (size_t)j[u] * HC + lane * 8);
#pragma unroll
        for (int u = 0; u < 8; u++) aL[u] = g_aL[j[u] * NHEADS + head];
#pragma unroll
        for (int u = 0; u < 8; u++) pd[u] = dot8(q[u], xi0, xi1);
#pragma unroll
        for (int u = 0; u < 8; u++) pd[u] += __shfl_xor_sync(0xffffffffu, pd[u], 1);
#pragma unroll
        for (int u = 0; u < 8; u++) pd[u] += __shfl_xor_sync(0xffffffffu, pd[u], 2);
#pragma unroll
        for (int u = 0; u < 8; u++) {
            float al = (aL[u] + aRi) * __fdividef(1.f, 1.f + __expf(-pd[u]));
            al = al > 0.f ? al : 0.2f * al;
            float wt = __expf(al);
            d += wt;
            axpy8(q[u], wt, a0, a1);
        }
    }
    for (; k < e; k++) {
        int j0 = g_csr[k];
        uint4 q0 = *(const uint4*)(h + (size_t)j0 * HC + lane * 8);
        float aL0 = g_aL[j0 * NHEADS + head];
        float pd0 = dot8(q0, xi0, xi1);
        pd0 += __shfl_xor_sync(0xffffffffu, pd0, 1);
        pd0 += __shfl_xor_sync(0xffffffffu, pd0, 2);
        float al0 = (aL0 + aRi) * __fdividef(1.f, 1.f + __expf(-pd0));
        al0 = al0 > 0.f ? al0 : 0.2f * al0;
        float w0 = __expf(al0);
        d += w0;
        axpy8(q0, w0, a0, a1);
    }
    float inv = 1.f / (d + 1e-16f);
    const float4* bp = (const float4*)(bias + lane * 8);
    float4 b0 = bp[0], b1 = bp[1];
    float4 o0, o1;
    o0.x = a0.x * inv + b0.x;  o0.y = a0.y * inv + b0.y;
    o0.z = a0.z * inv + b0.z;  o0.w = a0.w * inv + b0.w;
    o1.x = a1.x * inv + b1.x;  o1.y = a1.y * inv + b1.y;
    o1.z = a1.z * inv + b1.z;  o1.w = a1.w * inv + b1.w;
    if (applyElu) {
        o0.x = o0.x > 0.f ? o0.x : (__expf(o0.x) - 1.f);
        o0.y = o0.y > 0.f ? o0.y : (__expf(o0.y) - 1.f);
        o0.z = o0.z > 0.f ? o0.z : (__expf(o0.z) - 1.f);
        o0.w = o0.w > 0.f ? o0.w : (__expf(o0.w) - 1.f);
        o1.x = o1.x > 0.f ? o1.x : (__expf(o1.x) - 1.f);
        o1.y = o1.y > 0.f ? o1.y : (__expf(o1.y) - 1.f);
        o1.z = o1.z > 0.f ? o1.z : (__expf(o1.z) - 1.f);
        o1.w = o1.w > 0.f ? o1.w : (__expf(o1.w) - 1.f);
    }
    uint4 st;
    *(__half2*)&st.x = __floats2half2_rn(o0.x, o0.y);
    *(__half2*)&st.y = __floats2half2_rn(o0.z, o0.w);
    *(__half2*)&st.z = __floats2half2_rn(o1.x, o1.y);
    *(__half2*)&st.w = __floats2half2_rn(o1.z, o1.w);
    *(uint4*)&g_bufh[(size_t)w * HC + lane * 8] = st;
}

// ---------------- fused mean pool + classifier (batch is sorted) ----------------
__device__ __forceinline__ int lower_bound_batch(const void* batch, int val) {
    int lo = 0, hi = NN;
    while (lo < hi) {
        int mid = (lo + hi) >> 1;
        if (load_idx(batch, mid) < val) lo = mid + 1; else hi = mid;
    }
    return lo;
}

__global__ void pool_final_kernel(const void* __restrict__ batch,
                                  const float* __restrict__ linW,
                                  const float* __restrict__ linb,
                                  float* __restrict__ out) {
    int g = blockIdx.x, t = threadIdx.x;
    int lo = lower_bound_batch(batch, g);
    int hi = lower_bound_batch(batch, g + 1);
    float s = 0.f;
    int n = lo;
    for (; n + 3 < hi; n += 4) {
        s += __half2float(g_bufh[(size_t)n * HC + t])
           + __half2float(g_bufh[(size_t)(n + 1) * HC + t])
           + __half2float(g_bufh[(size_t)(n + 2) * HC + t])
           + __half2float(g_bufh[(size_t)(n + 3) * HC + t]);
    }
    for (; n < hi; n++) s += __half2float(g_bufh[(size_t)n * HC + t]);
    float cnt = (float)(hi - lo);
    __shared__ float sp[HC];
    sp[t] = s / fmaxf(cnt, 1.f);
    __syncthreads();
    if (t < NCLS) {
        float o = linb[t];
#pragma unroll 8
        for (int k = 0; k < HC; k++) o += sp[k] * linW[k * NCLS + t];
        out[g * NCLS + t] = o;
    }
}

// ---------------- launch ----------------
extern "C" void kernel_launch(void* const* d_in, const int* in_sizes, int n_in,
                              void* d_out, int out_size) {
    const float* x     = (const float*)d_in[0];
    const void*  ei    = d_in[1];
    const void*  batch = d_in[2];
    const float* W1    = (const float*)d_in[3];
    const float* attl1 = (const float*)d_in[4];
    const float* attr1 = (const float*)d_in[5];
    const float* b1    = (const float*)d_in[6];
    const float* W2    = (const float*)d_in[7];
    const float* attl2 = (const float*)d_in[8];
    const float* attr2 = (const float*)d_in[9];
    const float* b2    = (const float*)d_in[10];
    const float* linW  = (const float*)d_in[11];
    const float* linb  = (const float*)d_in[12];
    float*       out   = (float*)d_out;

    dim3 gg(HC / 64, (NN + 127) / 128);
    const int ATTN_BLOCKS = (NN * 32 + 255) / 256;
    const int EB4 = (ET / 4 + 255) / 256 + 1;

    // Fork a side stream so the CSR build overlaps with gemm1.
    cudaStream_t s2;
    cudaEvent_t eFork, eJoin;
    cudaStreamCreateWithFlags(&s2, cudaStreamNonBlocking);
    cudaEventCreateWithFlags(&eFork, cudaEventDisableTiming);
    cudaEventCreateWithFlags(&eJoin, cudaEventDisableTiming);

    cudaEventRecord(eFork, 0);
    cudaStreamWaitEvent(s2, eFork, 0);

    // side stream: CSR build chain
    init_kernel<<<(NN + 255) / 256, 256, 0, s2>>>((const int*)ei);
    hist_kernel<<<EB4, 256, 0, s2>>>(ei);
    scan_kernel<<<1, 1024, 0, s2>>>();
    // main stream: gemm1 (profiled slot)
    gemm_kernel<<<gg, 256>>>(x, W1, attl1, attr1, NN, FIN, 0);
    fill_kernel<<<EB4, 256, 0, s2>>>(ei);
    cudaEventRecord(eJoin, s2);
    cudaStreamWaitEvent(0, eJoin, 0);

    attn_kernel<<<ATTN_BLOCKS, 256>>>(b1, 1);
    gemm_kernel<<<gg, 256>>>(nullptr, W2, attl2, attr2, NN, HC, 1);
    attn_kernel<<<ATTN_BLOCKS, 256>>>(b2, 0);
    pool_final_kernel<<<NG, 256>>>(batch, linW, linb, out);
}